// round 1
// baseline (speedup 1.0000x reference)
#include <cuda_runtime.h>
#include <math.h>

// Shapes (fixed by the problem)
// B=4, N_TR=256, M_DET=1024, T=16, D=256, H=4, HD=64, N_FUSER=4, N_GNN=12, ITERS=100
#define P_TRK 16384   // (B*N_TR)*T
#define P_DET 4096    // B*M_DET
#define P_TR  1024    // B*N_TR
#define ZROW  263425  // 257*1025
#define NORM_C  (-7.1546153569136625f)  /* -ln(1280) */
#define LOG1024 6.931471805599453f
#define LOG256  5.545177444479562f

__device__ float g_pool[54000000];

// ---------------------------------------------------------------------------
// Generic 1x1-conv GEMM: out[o,p] = act( sum_i W[o,i]*X[i,p] + bias[o] + add[o,p] )
// X2 != null => rows i>=256 read from X2[i-256]. Requires O%64==0, I%16==0, P%64==0.
// ---------------------------------------------------------------------------
__global__ __launch_bounds__(256) void gemm_k(
    const float* __restrict__ W, const float* __restrict__ bias,
    const float* __restrict__ X, const float* __restrict__ X2,
    const float* __restrict__ addp, float* __restrict__ out,
    int I, int P, int relu)
{
    __shared__ float Ws[16][68];
    __shared__ float Xs[16][64];
    int tid = threadIdx.x;
    int tx = tid & 15, ty = tid >> 4;
    int pc = blockIdx.x * 64;
    int oc = blockIdx.y * 64;
    float acc[4][4] = {};
    for (int kc = 0; kc < I; kc += 16) {
#pragma unroll
        for (int r = 0; r < 4; r++) {
            int e = tid + r * 256;
            int ol = e >> 4, kl = e & 15;
            Ws[kl][ol] = W[(oc + ol) * I + kc + kl];
        }
#pragma unroll
        for (int r = 0; r < 4; r++) {
            int e = tid + r * 256;
            int kl = e >> 6, pl = e & 63;
            int gi = kc + kl;
            const float* src = (X2 != nullptr && gi >= 256) ? (X2 + (gi - 256) * P)
                                                            : (X + gi * P);
            Xs[kl][pl] = src[pc + pl];
        }
        __syncthreads();
#pragma unroll
        for (int kk = 0; kk < 16; kk++) {
            float a[4], b[4];
#pragma unroll
            for (int i = 0; i < 4; i++) a[i] = Ws[kk][ty * 4 + i];
#pragma unroll
            for (int j = 0; j < 4; j++) b[j] = Xs[kk][tx * 4 + j];
#pragma unroll
            for (int i = 0; i < 4; i++)
#pragma unroll
                for (int j = 0; j < 4; j++) acc[i][j] += a[i] * b[j];
        }
        __syncthreads();
    }
#pragma unroll
    for (int i = 0; i < 4; i++) {
        int o = oc + ty * 4 + i;
        float bv = bias ? bias[o] : 0.f;
#pragma unroll
        for (int j = 0; j < 4; j++) {
            int p = pc + tx * 4 + j;
            float v = acc[i][j] + bv;
            if (addp) v += addp[o * P + p];
            if (relu) v = fmaxf(v, 0.f);
            out[o * P + p] = v;
        }
    }
}

// ---------------------------------------------------------------------------
// Multi-head attention, HD=64, H=4. Feature layout [256, P], channel = hd*4+h.
// One thread per query, online softmax, key/value tiles of 64 in smem.
// grid: (ceil(nq/64), H, Bc), block 64.
// ---------------------------------------------------------------------------
__global__ __launch_bounds__(64) void attn_k(
    const float* __restrict__ qF, const float* __restrict__ kF,
    const float* __restrict__ vF, float* __restrict__ msg,
    int Pq, int Pk, int nq, int nk)
{
    __shared__ float ks[64][64];
    __shared__ float vs[64][64];
    int tid = threadIdx.x;
    int h = blockIdx.y;
    int bz = blockIdx.z;
    int ql = blockIdx.x * 64 + tid;
    bool active = ql < nq;
    int qpos = bz * nq + (active ? ql : 0);
    float qr[64];
#pragma unroll
    for (int hd = 0; hd < 64; hd++)
        qr[hd] = active ? qF[(hd * 4 + h) * Pq + qpos] : 0.f;
    float mx = -1e30f, sm = 0.f;
    float acc[64];
#pragma unroll
    for (int hd = 0; hd < 64; hd++) acc[hd] = 0.f;

    for (int kt = 0; kt < nk; kt += 64) {
        int m = kt + tid;
        bool kok = m < nk;
        int kpos = bz * nk + (kok ? m : 0);
#pragma unroll
        for (int hd = 0; hd < 64; hd++) {
            ks[hd][tid] = kok ? kF[(hd * 4 + h) * Pk + kpos] : 0.f;
            vs[hd][tid] = kok ? vF[(hd * 4 + h) * Pk + kpos] : 0.f;
        }
        __syncthreads();
        if (active) {
            int mmax = min(64, nk - kt);
            for (int ml = 0; ml < mmax; ml++) {
                float s = 0.f;
#pragma unroll
                for (int hd = 0; hd < 64; hd++) s += qr[hd] * ks[hd][ml];
                s *= 0.125f;  // 1/sqrt(64)
                float p;
                if (s > mx) {
                    float c = __expf(mx - s);
                    sm *= c;
#pragma unroll
                    for (int hd = 0; hd < 64; hd++) acc[hd] *= c;
                    mx = s;
                    p = 1.f;
                } else {
                    p = __expf(s - mx);
                }
                sm += p;
#pragma unroll
                for (int hd = 0; hd < 64; hd++) acc[hd] += p * vs[hd][ml];
            }
        }
        __syncthreads();
    }
    if (active) {
        float inv = 1.f / sm;
#pragma unroll
        for (int hd = 0; hd < 64; hd++)
            msg[(hd * 4 + h) * Pq + qpos] = acc[hd] * inv;
    }
}

// ---------------------------------------------------------------------------
// Input gathers + positional encodings + pooling
// ---------------------------------------------------------------------------
__global__ void gather_trk(const float* __restrict__ tracks, float* __restrict__ o)
{
    int idx = blockIdx.x * 256 + threadIdx.x;
    if (idx >= 256 * P_TRK) return;
    int c = idx >> 14, p = idx & 16383;
    int bi = p >> 4, t = p & 15;
    o[idx] = tracks[bi * 4112 + (c + 1) * 16 + t];
}
__global__ void gather_det(const float* __restrict__ det, float* __restrict__ o)
{
    int idx = blockIdx.x * 256 + threadIdx.x;
    if (idx >= 256 * P_DET) return;
    int c = idx >> 12, p = idx & 4095;
    int b = p >> 10, m = p & 1023;
    o[idx] = det[b * 263168 + (c + 1) * 1024 + m];
}
__global__ void pe_trk_k(const float* __restrict__ tracks, float* __restrict__ pe)
{
    int idx = blockIdx.x * 256 + threadIdx.x;
    if (idx >= 256 * P_TRK) return;
    int c = idx >> 14, p = idx & 16383;
    int bi = p >> 4, t = p & 15;
    float pos = tracks[bi * 4112 + t];
    float dv = expf((float)(c & ~1) * (-9.210340371976184f / 256.f));
    float ang = pos * dv;
    pe[idx] = (c & 1) ? cosf(ang) : sinf(ang);
}
__global__ void pe_det_k(const float* __restrict__ det, float* __restrict__ pe)
{
    int idx = blockIdx.x * 256 + threadIdx.x;
    if (idx >= 256 * P_DET) return;
    int c = idx >> 12, p = idx & 4095;
    int b = p >> 10, m = p & 1023;
    float pos = det[b * 263168 + m];
    float dv = expf((float)(c & ~1) * (-9.210340371976184f / 256.f));
    float ang = pos * dv;
    pe[idx] = (c & 1) ? cosf(ang) : sinf(ang);
}
__global__ void pool_k(const float* __restrict__ x, float* __restrict__ tr)
{
    int idx = blockIdx.x * 256 + threadIdx.x;
    if (idx >= 256 * P_TR) return;
    int c = idx >> 10, bi = idx & 1023;
    const float* p = x + c * P_TRK + bi * 16;
    float s = 0.f;
#pragma unroll
    for (int t = 0; t < 16; t++) s += p[t];
    tr[idx] = s * 0.0625f;
}

// ---------------------------------------------------------------------------
// scores[b,n,m] = (1/16) * sum_d m0[d, b*256+n] * m1[d, b*1024+m]  -> into Z0
// grid (16,4,4) = (mtiles, ntiles, b), block 256
// ---------------------------------------------------------------------------
__global__ __launch_bounds__(256) void scores_k(
    const float* __restrict__ m0, const float* __restrict__ m1, float* __restrict__ Z0)
{
    __shared__ float As[16][64];
    __shared__ float Bs[16][64];
    int tid = threadIdx.x, tx = tid & 15, ty = tid >> 4;
    int b = blockIdx.z;
    int nc = blockIdx.y * 64, mc = blockIdx.x * 64;
    float acc[4][4] = {};
    for (int kc = 0; kc < 256; kc += 16) {
#pragma unroll
        for (int r = 0; r < 4; r++) {
            int e = tid + r * 256;
            int kl = e >> 6, nl = e & 63;
            As[kl][nl] = m0[(kc + kl) * P_TR + b * 256 + nc + nl];
        }
#pragma unroll
        for (int r = 0; r < 4; r++) {
            int e = tid + r * 256;
            int kl = e >> 6, ml = e & 63;
            Bs[kl][ml] = m1[(kc + kl) * P_DET + b * 1024 + mc + ml];
        }
        __syncthreads();
#pragma unroll
        for (int kk = 0; kk < 16; kk++) {
            float a[4], bb[4];
#pragma unroll
            for (int i = 0; i < 4; i++) a[i] = As[kk][ty * 4 + i];
#pragma unroll
            for (int j = 0; j < 4; j++) bb[j] = Bs[kk][tx * 4 + j];
#pragma unroll
            for (int i = 0; i < 4; i++)
#pragma unroll
                for (int j = 0; j < 4; j++) acc[i][j] += a[i] * bb[j];
        }
        __syncthreads();
    }
#pragma unroll
    for (int i = 0; i < 4; i++) {
        int n = nc + ty * 4 + i;
#pragma unroll
        for (int j = 0; j < 4; j++) {
            int m = mc + tx * 4 + j;
            Z0[b * ZROW + n * 1025 + m] = acc[i][j] * 0.0625f;
        }
    }
}

__global__ void fill_bins(float* __restrict__ Z0, const float* __restrict__ alpha_p)
{
    float a = *alpha_p;
    int idx = blockIdx.x * 256 + threadIdx.x;
    if (idx < 1024) {  // last column for rows < 256
        int b = idx >> 8, i = idx & 255;
        Z0[b * ZROW + i * 1025 + 1024] = a;
    }
    int idx2 = idx - 1024;
    if (idx2 >= 0 && idx2 < 4100) {  // full last row (incl. corner)
        int b = idx2 / 1025, j = idx2 % 1025;
        Z0[b * ZROW + 256 * 1025 + j] = a;
    }
}

__global__ void zero_k(float* p, int n)
{
    int i = blockIdx.x * 256 + threadIdx.x;
    if (i < n) p[i] = 0.f;
}

// ---------------------------------------------------------------------------
// Sinkhorn (log domain, online logsumexp)
// ---------------------------------------------------------------------------
__device__ __forceinline__ void lse_merge(float& m, float& s, float om, float os)
{
    float M = fmaxf(m, om);
    s = s * __expf(m - M) + os * __expf(om - M);
    m = M;
}

__global__ __launch_bounds__(256) void sink_u(
    const float* __restrict__ Z0, const float* __restrict__ v, float* __restrict__ u)
{
    int row = blockIdx.x;  // 0..1027
    int b = row / 257, i = row % 257;
    const float* zr = Z0 + b * ZROW + i * 1025;
    const float* vb = v + b * 1025;
    float m = -1e30f, s = 0.f;
    for (int j = threadIdx.x; j < 1025; j += 256) {
        float z = zr[j] + vb[j];
        if (z > m) { s = s * __expf(m - z) + 1.f; m = z; }
        else s += __expf(z - m);
    }
    for (int off = 16; off; off >>= 1) {
        float om = __shfl_down_sync(0xffffffffu, m, off);
        float os = __shfl_down_sync(0xffffffffu, s, off);
        lse_merge(m, s, om, os);
    }
    __shared__ float smm[8], sss[8];
    int w = threadIdx.x >> 5, l = threadIdx.x & 31;
    if (l == 0) { smm[w] = m; sss[w] = s; }
    __syncthreads();
    if (threadIdx.x == 0) {
        m = smm[0]; s = sss[0];
        for (int k = 1; k < 8; k++) lse_merge(m, s, smm[k], sss[k]);
        float logmu = (i < 256) ? NORM_C : (NORM_C + LOG1024);
        u[row] = logmu - (m + __logf(s));
    }
}

__global__ __launch_bounds__(256) void sink_v(
    const float* __restrict__ Z0, const float* __restrict__ u, float* __restrict__ v)
{
    int b = blockIdx.y;
    int c = threadIdx.x & 31;
    int j = blockIdx.x * 32 + c;
    int g = threadIdx.x >> 5;  // 8 row groups
    float m = -1e30f, s = 0.f;
    if (j < 1025) {
        const float* zb = Z0 + b * ZROW;
        const float* ub = u + b * 257;
        for (int i = g; i < 257; i += 8) {
            float z = zb[i * 1025 + j] + ub[i];
            if (z > m) { s = s * __expf(m - z) + 1.f; m = z; }
            else s += __expf(z - m);
        }
    }
    __shared__ float smm[8][33], sss[8][33];
    smm[g][c] = m; sss[g][c] = s;
    __syncthreads();
    if (g == 0 && j < 1025) {
        m = smm[0][c]; s = sss[0][c];
        for (int k = 1; k < 8; k++) lse_merge(m, s, smm[k][c], sss[k][c]);
        float lognu = (j < 1024) ? NORM_C : (NORM_C + LOG256);
        v[b * 1025 + j] = lognu - (m + __logf(s));
    }
}

__global__ void sink_out(const float* __restrict__ Z0, const float* __restrict__ u,
                         const float* __restrict__ v, float* __restrict__ out)
{
    int idx = blockIdx.x * 256 + threadIdx.x;
    if (idx >= 4 * ZROW) return;
    int b = idx / ZROW;
    int r = idx - b * ZROW;
    int i = r / 1025, j = r - i * 1025;
    out[idx] = Z0[idx] + u[b * 257 + i] + v[b * 1025 + j] - NORM_C;
}

// ---------------------------------------------------------------------------
// Host orchestration
// ---------------------------------------------------------------------------
static void gemm(const float* W, const float* bias, const float* X, const float* X2,
                 const float* addp, float* out, int O, int I, int P, int relu)
{
    dim3 g(P / 64, O / 64);
    gemm_k<<<g, 256>>>(W, bias, X, X2, addp, out, I, P, relu);
}

extern "C" void kernel_launch(void* const* d_in, const int* in_sizes, int n_in,
                              void* d_out, int out_size)
{
    const float* detections = (const float*)d_in[0];
    const float* tracks     = (const float*)d_in[1];
    const float* enc_w1 = (const float*)d_in[2];
    const float* enc_b1 = (const float*)d_in[3];
    const float* enc_w2 = (const float*)d_in[4];
    const float* enc_b2 = (const float*)d_in[5];
    const float* fus_pw  = (const float*)d_in[6];
    const float* fus_pb  = (const float*)d_in[7];
    const float* fus_mw  = (const float*)d_in[8];
    const float* fus_mb  = (const float*)d_in[9];
    const float* fus_m1w = (const float*)d_in[10];
    const float* fus_m1b = (const float*)d_in[11];
    const float* fus_m2w = (const float*)d_in[12];
    const float* fus_m2b = (const float*)d_in[13];
    const float* gnn_pw  = (const float*)d_in[14];
    const float* gnn_pb  = (const float*)d_in[15];
    const float* gnn_mw  = (const float*)d_in[16];
    const float* gnn_mb  = (const float*)d_in[17];
    const float* gnn_m1w = (const float*)d_in[18];
    const float* gnn_m1b = (const float*)d_in[19];
    const float* gnn_m2w = (const float*)d_in[20];
    const float* gnn_m2b = (const float*)d_in[21];
    const float* final_w = (const float*)d_in[22];
    const float* final_b = (const float*)d_in[23];
    const float* bin_score = (const float*)d_in[24];
    float* out = (float*)d_out;

    float* pool = nullptr;
    cudaGetSymbolAddress((void**)&pool, g_pool);
    size_t off = 0;
    auto carve = [&](size_t n) { float* p = pool + off; off += n; return p; };
    float* TRKIN = carve(4194304);
    float* DETIN = carve(1048576);
    float* TRKPE = carve(4194304);
    float* DETPE = carve(1048576);
    float* TMP1  = carve(8388608);
    float* QBUF  = carve(4194304);
    float* KV    = carve(8388608);
    float* MSG   = carve(4194304);
    float* MSG2  = carve(4194304);
    float* XA    = carve(4194304);
    float* XB    = carve(4194304);
    float* DETA  = carve(1048576);
    float* DETB  = carve(1048576);
    float* TRA   = carve(262144);
    float* TRB   = carve(262144);
    float* M0b   = carve(262144);
    float* M1b   = carve(1048576);
    float* Z0    = carve(1053700);
    float* U     = carve(1028);
    float* V     = carve(4100);

    // ---- input gathers + positional encodings ----
    gather_trk<<<16384, 256>>>(tracks, TRKIN);
    gather_det<<<4096, 256>>>(detections, DETIN);
    pe_trk_k<<<16384, 256>>>(tracks, TRKPE);
    pe_det_k<<<4096, 256>>>(detections, DETPE);

    // ---- encoders (enc + pe add folded into second GEMM) ----
    gemm(enc_w1, enc_b1, TRKIN, nullptr, nullptr, TMP1, 256, 256, P_TRK, 1);
    gemm(enc_w2, enc_b2, TMP1, nullptr, TRKPE, XA, 256, 256, P_TRK, 0);
    gemm(enc_w1, enc_b1, DETIN, nullptr, nullptr, TMP1, 256, 256, P_DET, 1);
    gemm(enc_w2, enc_b2, TMP1, nullptr, DETPE, DETA, 256, 256, P_DET, 0);

    // ---- fuser: 4 self-attention layers over T=16 per track ----
    float* x = XA; float* xo = XB;
    for (int l = 0; l < 4; l++) {
        const float* pw = fus_pw + l * 196608;
        const float* pb = fus_pb + l * 768;
        gemm(pw, pb, x, nullptr, nullptr, QBUF, 256, 256, P_TRK, 0);
        gemm(pw + 65536, pb + 256, x, nullptr, nullptr, KV, 512, 256, P_TRK, 0);
        attn_k<<<dim3(1, 4, 1024), 64>>>(QBUF, KV, KV + 256 * P_TRK, MSG,
                                         P_TRK, P_TRK, 16, 16);
        gemm(fus_mw + l * 65536, fus_mb + l * 256, MSG, nullptr, nullptr, MSG2,
             256, 256, P_TRK, 0);
        gemm(fus_m1w + l * 262144, fus_m1b + l * 512, x, MSG2, nullptr, TMP1,
             512, 512, P_TRK, 1);
        gemm(fus_m2w + l * 131072, fus_m2b + l * 256, TMP1, nullptr, x, xo,
             256, 512, P_TRK, 0);
        float* t = x; x = xo; xo = t;
    }
    pool_k<<<1024, 256>>>(x, TRA);

    // ---- GNN: 12 alternating self/cross layers ----
    float* tr = TRA; float* tro = TRB;
    float* de = DETA; float* deo = DETB;
    for (int l = 0; l < 12; l++) {
        const float* pw  = gnn_pw + l * 196608;
        const float* pb  = gnn_pb + l * 768;
        const float* mw  = gnn_mw + l * 65536;
        const float* mb  = gnn_mb + l * 256;
        const float* m1w = gnn_m1w + l * 262144;
        const float* m1b = gnn_m1b + l * 512;
        const float* m2w = gnn_m2w + l * 131072;
        const float* m2b = gnn_m2b + l * 256;
        int cross = l & 1;

        // d0: queries = tr, source = cross ? det : tr
        const float* s0 = cross ? de : tr;
        int P0 = cross ? P_DET : P_TR;
        int nk0 = cross ? 1024 : 256;
        gemm(pw, pb, tr, nullptr, nullptr, QBUF, 256, 256, P_TR, 0);
        gemm(pw + 65536, pb + 256, s0, nullptr, nullptr, KV, 512, 256, P0, 0);
        attn_k<<<dim3(4, 4, 4), 64>>>(QBUF, KV, KV + 256 * P0, MSG, P_TR, P0, 256, nk0);
        gemm(mw, mb, MSG, nullptr, nullptr, MSG2, 256, 256, P_TR, 0);
        gemm(m1w, m1b, tr, MSG2, nullptr, TMP1, 512, 512, P_TR, 1);
        gemm(m2w, m2b, TMP1, nullptr, tr, tro, 256, 512, P_TR, 0);

        // d1: queries = det, source = cross ? tr : det  (uses OLD tr)
        const float* s1 = cross ? tr : de;
        int P1 = cross ? P_TR : P_DET;
        int nk1 = cross ? 256 : 1024;
        gemm(pw, pb, de, nullptr, nullptr, QBUF, 256, 256, P_DET, 0);
        gemm(pw + 65536, pb + 256, s1, nullptr, nullptr, KV, 512, 256, P1, 0);
        attn_k<<<dim3(16, 4, 4), 64>>>(QBUF, KV, KV + 256 * P1, MSG, P_DET, P1, 1024, nk1);
        gemm(mw, mb, MSG, nullptr, nullptr, MSG2, 256, 256, P_DET, 0);
        gemm(m1w, m1b, de, MSG2, nullptr, TMP1, 512, 512, P_DET, 1);
        gemm(m2w, m2b, TMP1, nullptr, de, deo, 256, 512, P_DET, 0);

        float* t = tr; tr = tro; tro = t;
        t = de; de = deo; deo = t;
    }

    // ---- final projections + scores + Sinkhorn ----
    gemm(final_w, final_b, tr, nullptr, nullptr, M0b, 256, 256, P_TR, 0);
    gemm(final_w, final_b, de, nullptr, nullptr, M1b, 256, 256, P_DET, 0);
    scores_k<<<dim3(16, 4, 4), 256>>>(M0b, M1b, Z0);
    fill_bins<<<21, 256>>>(Z0, bin_score);
    zero_k<<<21, 256>>>(U, 5128);  // U (1028) and V (4100) are contiguous

    for (int it = 0; it < 100; it++) {
        sink_u<<<1028, 256>>>(Z0, V, U);
        sink_v<<<dim3(33, 4), 256>>>(Z0, U, V);
    }
    sink_out<<<(4 * ZROW + 255) / 256, 256>>>(Z0, U, V, out);
    (void)in_sizes; (void)n_in; (void)out_size;
}